// round 7
// baseline (speedup 1.0000x reference)
#include <cuda_runtime.h>

#define KBATCH 64
#define NN 1024
#define DIN 16
#define H1D 4
#define DOUT 8
#define FC1D 54

typedef unsigned long long ull;

// ---------------- scratch (static device memory) ----------------
__device__ unsigned g_adjP[NN * 256];      // byte-mask words, j-pair layout (see prologue)
__device__ ull g_h1a[KBATCH * NN * 2];     // layer1 h pairs AoS: [kn][2] = {h0,h1},{h2,h3}
__device__ ull g_h2a[KBATCH * NN * 4];     // layer2 h pairs AoS: [kn][4]
__device__ ull g_f1p1[KBATCH * NN];        // {e^f1, e^{0.01 f1}}
__device__ ull g_f2p1[KBATCH * NN];
__device__ ull g_f1p2[KBATCH * NN];
__device__ ull g_f2p2[KBATCH * NN];
__device__ ull g_g4[KBATCH * NN * 4];      // relu(gat2) pairs == [K][8192] floats
__device__ float g_xp[128 * FC1D * KBATCH]; // fc1 partials [dchunk][c][k]

// ---------------- f32x2 helpers ----------------
__device__ __forceinline__ ull mul2(ull a, ull b) {
    ull r; asm("mul.rn.f32x2 %0,%1,%2;" : "=l"(r) : "l"(a), "l"(b)); return r;
}
__device__ __forceinline__ ull fma2(ull a, ull b, ull c) {
    ull r; asm("fma.rn.f32x2 %0,%1,%2,%3;" : "=l"(r) : "l"(a), "l"(b), "l"(c)); return r;
}
__device__ __forceinline__ ull add2(ull a, ull b) {
    ull r; asm("add.rn.f32x2 %0,%1,%2;" : "=l"(r) : "l"(a), "l"(b)); return r;
}
__device__ __forceinline__ float lo2(ull v) { return __uint_as_float((unsigned)v); }
__device__ __forceinline__ float hi2(ull v) { return __uint_as_float((unsigned)(v >> 32)); }
__device__ __forceinline__ ull pk(float x, float y) {
    ull r; asm("mov.b64 %0,{%1,%2};" : "=l"(r) : "r"(__float_as_uint(x)), "r"(__float_as_uint(y))); return r;
}
__device__ __forceinline__ ull pku(unsigned x, unsigned y) {
    ull r; asm("mov.b64 %0,{%1,%2};" : "=l"(r) : "r"(x), "r"(y)); return r;
}
__device__ __forceinline__ ull bcast2(unsigned v) {
    ull r; asm("mov.b64 %0,{%1,%1};" : "=l"(r) : "r"(v)); return r;
}
__device__ __forceinline__ ull shfl2(ull v, int o) {
    unsigned l = (unsigned)v, h = (unsigned)(v >> 32);
    l = __shfl_xor_sync(0xffffffffu, l, o);
    h = __shfl_xor_sync(0xffffffffu, h, o);
    return (ull)l | ((ull)h << 32);
}

// ---------------- prologue: pack adj bytes (j-pair layout) + prep1 ----------------
// word(i,g,lane): b0 = adj[i][g*128 + 2*lane], b1 = +1,
//                 b2 = adj[i][g*128 + 64 + 2*lane], b3 = +1  (0xFF / 0x00)
__global__ void prologue_kernel(const int* __restrict__ adj,
                                const float* __restrict__ X,
                                const float* __restrict__ W1,
                                const float* __restrict__ a1) {
    __shared__ float w[DIN * H1D];
    __shared__ float a[2 * H1D];
    int b = blockIdx.x, t = threadIdx.x;
    if (b < 256) {
#pragma unroll
        for (int ww = 0; ww < 4; ww++) {
            int idx = (b << 10) + (t << 2) + ww;        // word index, 256 per i
            int i = idx >> 8, g = (idx >> 5) & 7, lane = idx & 31;
            const int* row = adj + i * NN + g * 128 + 2 * lane;
            unsigned b0 = row[0] > 0 ? 0xFFu : 0u;
            unsigned b1 = row[1] > 0 ? 0xFFu : 0u;
            unsigned b2 = row[64] > 0 ? 0xFFu : 0u;
            unsigned b3 = row[65] > 0 ? 0xFFu : 0u;
            g_adjP[idx] = b0 | (b1 << 8) | (b2 << 16) | (b3 << 24);
        }
    } else {
        if (t < DIN * H1D) w[t] = W1[t];
        if (t < 2 * H1D) a[t] = a1[t];
        __syncthreads();
        int kn = (b - 256) * 256 + t;
        const float4* x4 = reinterpret_cast<const float4*>(X) + kn * 4;
        float h[H1D] = {0.f, 0.f, 0.f, 0.f};
#pragma unroll
        for (int q = 0; q < 4; q++) {
            float4 xv = x4[q];
            float xs[4] = {xv.x, xv.y, xv.z, xv.w};
#pragma unroll
            for (int d = 0; d < 4; d++)
#pragma unroll
                for (int c = 0; c < H1D; c++)
                    h[c] += xs[d] * w[(q * 4 + d) * H1D + c];
        }
        float f1 = 0.f, f2 = 0.f;
#pragma unroll
        for (int c = 0; c < H1D; c++) { f1 += h[c] * a[c]; f2 += h[c] * a[H1D + c]; }
        g_h1a[kn * 2 + 0] = pk(h[0], h[1]);
        g_h1a[kn * 2 + 1] = pk(h[2], h[3]);
        g_f1p1[kn] = pk(__expf(f1), __expf(0.01f * f1));
        g_f2p1[kn] = pk(__expf(f2), __expf(0.01f * f2));
    }
}

// ---------------- attention: j-pair-packed f32x2, byte masks ----------------
// LAYER 1: CH=4 (fuses layer-2 projection epilogue). LAYER 2: CH=8.
template <int LAYER>
__global__ void __launch_bounds__(256) attn_kernel(const float* __restrict__ W2,
                                                   const float* __restrict__ a2) {
    constexpr int CH = (LAYER == 1) ? 4 : 8;
    constexpr int C2 = CH / 2;
    constexpr int RPW = 4;
    __shared__ ulonglong2 fs2[NN / 2];          // [j2] = { {efx_j0,efx_j1}, {efy_j0,efy_j1} }
    __shared__ ulonglong2 v2[C2][NN / 2];       // [c2][j2] = { {h2c2 pair}, {h2c2+1 pair} }
    __shared__ float w2s[H1D * DOUT + 2 * DOUT];

    const int k = blockIdx.y;
    const int tid = threadIdx.x;

    const ull* f2p = ((LAYER == 1) ? g_f2p1 : g_f2p2) + k * NN;
    const ull* ha  = (LAYER == 1) ? g_h1a : g_h2a;
    for (int j2 = tid; j2 < NN / 2; j2 += 256) {
        const int j0 = 2 * j2;
        ull fa = f2p[j0], fb = f2p[j0 + 1];
        ulonglong2 fv;
        fv.x = pk(lo2(fa), lo2(fb));
        fv.y = pk(hi2(fa), hi2(fb));
        fs2[j2] = fv;
#pragma unroll
        for (int c2 = 0; c2 < C2; c2++) {
            ull u0 = ha[(k * NN + j0) * C2 + c2];
            ull u1 = ha[(k * NN + j0 + 1) * C2 + c2];
            ulonglong2 hv;
            hv.x = pk(lo2(u0), lo2(u1));
            hv.y = pk(hi2(u0), hi2(u1));
            v2[c2][j2] = hv;
        }
    }
    if (LAYER == 1 && tid < H1D * DOUT + 2 * DOUT)
        w2s[tid] = (tid < H1D * DOUT) ? W2[tid] : a2[tid - H1D * DOUT];
    __syncthreads();

    const int warp = tid >> 5, lane = tid & 31;
    const int i0 = blockIdx.x * (8 * RPW) + warp * RPW;

    const ull* f1p = (LAYER == 1) ? g_f1p1 : g_f1p2;
    ull e1x[RPW], e1y[RPW], z2[RPW], acc[RPW][CH];
#pragma unroll
    for (int r = 0; r < RPW; r++) {
        ull e = f1p[k * NN + i0 + r];
        e1x[r] = bcast2((unsigned)e);
        e1y[r] = bcast2((unsigned)(e >> 32));
        z2[r] = 0ull;
#pragma unroll
        for (int c = 0; c < CH; c++) acc[r][c] = 0ull;
    }

#pragma unroll 4
    for (int g = 0; g < 8; g++) {
        unsigned aw[RPW];
#pragma unroll
        for (int r = 0; r < RPW; r++)
            aw[r] = g_adjP[(i0 + r) * 256 + g * 32 + lane];
#pragma unroll
        for (int half = 0; half < 2; half++) {
            const int j2 = g * 64 + half * 32 + lane;
            const unsigned sel0 = half ? 0x2222u : 0x0000u;
            const unsigned sel1 = half ? 0x3333u : 0x1111u;
            ulonglong2 fv = fs2[j2];
            ulonglong2 hv[C2];
#pragma unroll
            for (int c2 = 0; c2 < C2; c2++) hv[c2] = v2[c2][j2];
#pragma unroll
            for (int r = 0; r < RPW; r++) {
                ull A2 = mul2(e1x[r], fv.x);
                ull B2 = mul2(e1y[r], fv.y);
                float pl = fmaxf(lo2(A2), lo2(B2));   // exp(leaky_relu) for j0
                float ph = fmaxf(hi2(A2), hi2(B2));   // for j1
                unsigned m0 = __byte_perm(aw[r], 0, sel0);
                unsigned m1 = __byte_perm(aw[r], 0, sel1);
                ull p2 = pku(__float_as_uint(pl) & m0, __float_as_uint(ph) & m1);
                z2[r] = add2(z2[r], p2);
#pragma unroll
                for (int c2 = 0; c2 < C2; c2++) {
                    acc[r][2 * c2 + 0] = fma2(p2, hv[c2].x, acc[r][2 * c2 + 0]);
                    acc[r][2 * c2 + 1] = fma2(p2, hv[c2].y, acc[r][2 * c2 + 1]);
                }
            }
        }
    }

    // fold j-halves, then butterfly on channel-packed pairs
    float zf[RPW];
    ull ap[RPW][C2];
#pragma unroll
    for (int r = 0; r < RPW; r++) {
        zf[r] = lo2(z2[r]) + hi2(z2[r]);
#pragma unroll
        for (int c2 = 0; c2 < C2; c2++) {
            float a0 = lo2(acc[r][2 * c2]) + hi2(acc[r][2 * c2]);
            float a1 = lo2(acc[r][2 * c2 + 1]) + hi2(acc[r][2 * c2 + 1]);
            ap[r][c2] = pk(a0, a1);
        }
    }
#pragma unroll
    for (int o = 16; o; o >>= 1) {
#pragma unroll
        for (int r = 0; r < RPW; r++) {
            zf[r] += __shfl_xor_sync(0xffffffffu, zf[r], o);
#pragma unroll
            for (int c2 = 0; c2 < C2; c2++) ap[r][c2] = add2(ap[r][c2], shfl2(ap[r][c2], o));
        }
    }

    if (lane < RPW) {
        float Z = 0.f;
        ull A[C2];
#pragma unroll
        for (int r = 0; r < RPW; r++)
            if (lane == r) {
                Z = zf[r];
#pragma unroll
                for (int c2 = 0; c2 < C2; c2++) A[c2] = ap[r][c2];
            }
        float invz = (Z > 0.f) ? 1.f / Z : 0.f;
        float hv[CH];
#pragma unroll
        for (int c2 = 0; c2 < C2; c2++) {
            hv[2 * c2 + 0] = fmaxf(lo2(A[c2]) * invz, 0.f);
            hv[2 * c2 + 1] = fmaxf(hi2(A[c2]) * invz, 0.f);
        }
        const int gi = k * NN + i0 + lane;
        if (LAYER == 1) {
            float hh[DOUT];
#pragma unroll
            for (int o = 0; o < DOUT; o++)
                hh[o] = hv[0] * w2s[o] + hv[1] * w2s[DOUT + o] + hv[2] * w2s[2 * DOUT + o] + hv[3] * w2s[3 * DOUT + o];
            float f1 = 0.f, f2 = 0.f;
#pragma unroll
            for (int o = 0; o < DOUT; o++) {
                f1 += hh[o] * w2s[H1D * DOUT + o];
                f2 += hh[o] * w2s[H1D * DOUT + DOUT + o];
            }
#pragma unroll
            for (int c2 = 0; c2 < 4; c2++)
                g_h2a[gi * 4 + c2] = pk(hh[2 * c2], hh[2 * c2 + 1]);
            g_f1p2[gi] = pk(__expf(f1), __expf(0.01f * f1));
            g_f2p2[gi] = pk(__expf(f2), __expf(0.01f * f2));
        } else {
#pragma unroll
            for (int c2 = 0; c2 < C2; c2++)
                g_g4[gi * 4 + c2] = pk(hv[2 * c2], hv[2 * c2 + 1]);
        }
    }
}

// ---------------- head: fc1 split-K GEMM, partial outputs (no atomics) ----------------
#define FBLK 64
__global__ void __launch_bounds__(256) head_fc1_kernel(const float* __restrict__ fc1w) {
    __shared__ float gs[KBATCH][FBLK + 1];
    __shared__ float ws[FBLK][56];
    const int t = threadIdx.x;
    const int d0 = blockIdx.x * FBLK;
    const float* gg = reinterpret_cast<const float*>(g_g4);

#pragma unroll
    for (int idx = t; idx < KBATCH * (FBLK / 4); idx += 256) {
        int k = idx / (FBLK / 4), v = idx % (FBLK / 4);
        float4 x = *reinterpret_cast<const float4*>(gg + k * (NN * DOUT) + d0 + 4 * v);
        gs[k][4 * v + 0] = x.x; gs[k][4 * v + 1] = x.y;
        gs[k][4 * v + 2] = x.z; gs[k][4 * v + 3] = x.w;
    }
    for (int idx = t; idx < FBLK * FC1D; idx += 256) {
        int d = idx / FC1D, c = idx % FC1D;
        ws[d][c] = fc1w[d0 * FC1D + idx];
    }
    __syncthreads();

    const int k = t & 63;
    const int cg = t >> 6;
    ull acc[7] = {0ull, 0ull, 0ull, 0ull, 0ull, 0ull, 0ull};

#pragma unroll 4
    for (int d = 0; d < FBLK; d++) {
        ull g2 = bcast2(__float_as_uint(gs[k][d]));
        const ull* w2 = reinterpret_cast<const ull*>(&ws[d][cg * 14]);
#pragma unroll
        for (int q = 0; q < 7; q++) acc[q] = fma2(g2, w2[q], acc[q]);
    }

    float* dst = g_xp + (size_t)blockIdx.x * FC1D * KBATCH;
    const int cbase = cg * 14;
#pragma unroll
    for (int q = 0; q < 7; q++) {
        int c = cbase + 2 * q;
        if (c < FC1D)     dst[c * KBATCH + k] = lo2(acc[q]);
        if (c + 1 < FC1D) dst[(c + 1) * KBATCH + k] = hi2(acc[q]);
    }
}

// ---------------- head_out: reduce partials + bias/relu + GEMV ----------------
__global__ void __launch_bounds__(256) head_out_kernel(const float* __restrict__ fc1b,
                                                       const float* __restrict__ outw,
                                                       const float* __restrict__ outb,
                                                       float* __restrict__ out) {
    __shared__ float part[4][FC1D];
    __shared__ float xs[FC1D];
    const int k = blockIdx.y;
    const int t = threadIdx.x;

    if (t < 4 * FC1D) {
        const int c = t % FC1D, q = t / FC1D;
        float s = 0.f;
#pragma unroll 8
        for (int d = q * 32; d < q * 32 + 32; d++)
            s += g_xp[((size_t)d * FC1D + c) * KBATCH + k];
        part[q][c] = s;
    }
    __syncthreads();
    if (t < FC1D)
        xs[t] = fmaxf(part[0][t] + part[1][t] + part[2][t] + part[3][t] + fc1b[t], 0.f);
    __syncthreads();

    const int n = blockIdx.x * 256 + t;
    float s = outb[n];
#pragma unroll
    for (int c = 0; c < FC1D; c++) s += xs[c] * outw[c * NN + n];
    out[k * NN + n] = s;
}

// ---------------- launch ----------------
extern "C" void kernel_launch(void* const* d_in, const int* in_sizes, int n_in,
                              void* d_out, int out_size) {
    const float* X    = (const float*)d_in[0];
    const int*   adj  = (const int*)d_in[1];
    const float* W1   = (const float*)d_in[2];
    const float* a1   = (const float*)d_in[3];
    const float* W2   = (const float*)d_in[4];
    const float* a2   = (const float*)d_in[5];
    const float* fc1w = (const float*)d_in[6];
    const float* fc1b = (const float*)d_in[7];
    const float* outw = (const float*)d_in[8];
    const float* outb = (const float*)d_in[9];
    float* out = (float*)d_out;

    prologue_kernel<<<512, 256>>>(adj, X, W1, a1);
    {
        dim3 grid(NN / 32, KBATCH);
        attn_kernel<1><<<grid, 256>>>(W2, a2);
        attn_kernel<2><<<grid, 256>>>(W2, a2);
    }
    head_fc1_kernel<<<(NN * DOUT) / FBLK, 256>>>(fc1w);
    {
        dim3 grid(NN / 256, KBATCH);
        head_out_kernel<<<grid, 256>>>(fc1b, outw, outb, out);
    }
}

// round 8
// speedup vs baseline: 1.7697x; 1.7697x over previous
#include <cuda_runtime.h>

#define KBATCH 64
#define NN 1024
#define DIN 16
#define H1D 4
#define DOUT 8
#define FC1D 54

typedef unsigned long long ull;

// ---------------- scratch (static device memory) ----------------
__device__ unsigned g_adjT[NN * 32];            // word (i,l) bit jj = adj[i][jj*32+l]
__device__ ull g_h1q[2 * KBATCH * NN];          // layer1 h pairs, SoA: [q][k*N+n]
__device__ ull g_h2q[4 * KBATCH * NN];          // layer2 h pairs, SoA
__device__ ull g_f1p1[KBATCH * NN];             // {e^f1, e^{0.01 f1}}
__device__ ull g_f2p1[KBATCH * NN];
__device__ ull g_f1p2[KBATCH * NN];
__device__ ull g_f2p2[KBATCH * NN];
__device__ ull g_g4[KBATCH * NN * 4];           // relu(gat2) pairs == [K][8192] floats
__device__ float g_xp[128 * FC1D * KBATCH];     // fc1 partials [dchunk][c][k]

// ---------------- f32x2 helpers ----------------
__device__ __forceinline__ ull mul2(ull a, ull b) {
    ull r; asm("mul.rn.f32x2 %0,%1,%2;" : "=l"(r) : "l"(a), "l"(b)); return r;
}
__device__ __forceinline__ ull fma2(ull a, ull b, ull c) {
    ull r; asm("fma.rn.f32x2 %0,%1,%2,%3;" : "=l"(r) : "l"(a), "l"(b), "l"(c)); return r;
}
__device__ __forceinline__ ull add2(ull a, ull b) {
    ull r; asm("add.rn.f32x2 %0,%1,%2;" : "=l"(r) : "l"(a), "l"(b)); return r;
}
__device__ __forceinline__ float lo2(ull v) { return __uint_as_float((unsigned)v); }
__device__ __forceinline__ float hi2(ull v) { return __uint_as_float((unsigned)(v >> 32)); }
__device__ __forceinline__ ull pk(float x, float y) {
    return (ull)__float_as_uint(x) | ((ull)__float_as_uint(y) << 32);
}
__device__ __forceinline__ ull bcast2(unsigned v) {
    ull r; asm("mov.b64 %0,{%1,%1};" : "=l"(r) : "r"(v)); return r;
}
__device__ __forceinline__ ull shfl2(ull v, int o) {
    unsigned l = (unsigned)v, h = (unsigned)(v >> 32);
    l = __shfl_xor_sync(0xffffffffu, l, o);
    h = __shfl_xor_sync(0xffffffffu, h, o);
    return (ull)l | ((ull)h << 32);
}

// ---------------- prologue: pack adj + prep1 ----------------
__global__ void prologue_kernel(const int* __restrict__ adj,
                                const float* __restrict__ X,
                                const float* __restrict__ W1,
                                const float* __restrict__ a1) {
    __shared__ float w[DIN * H1D];
    __shared__ float a[2 * H1D];
    int b = blockIdx.x, t = threadIdx.x;
    if (b < 128) {
        int warp = t >> 5, lane = t & 31;
        int i = b * 8 + warp;
        unsigned acc = 0;
#pragma unroll
        for (int jj = 0; jj < 32; jj++) {
            int v = adj[i * NN + jj * 32 + lane];
            acc |= (v > 0 ? 1u : 0u) << jj;
        }
        g_adjT[i * 32 + lane] = acc;
    } else {
        if (t < DIN * H1D) w[t] = W1[t];
        if (t < 2 * H1D) a[t] = a1[t];
        __syncthreads();
        int kn = (b - 128) * 256 + t;
        const float4* x4 = reinterpret_cast<const float4*>(X) + kn * 4;
        float h[H1D] = {0.f, 0.f, 0.f, 0.f};
#pragma unroll
        for (int q = 0; q < 4; q++) {
            float4 xv = x4[q];
            float xs[4] = {xv.x, xv.y, xv.z, xv.w};
#pragma unroll
            for (int d = 0; d < 4; d++)
#pragma unroll
                for (int c = 0; c < H1D; c++)
                    h[c] += xs[d] * w[(q * 4 + d) * H1D + c];
        }
        float f1 = 0.f, f2 = 0.f;
#pragma unroll
        for (int c = 0; c < H1D; c++) { f1 += h[c] * a[c]; f2 += h[c] * a[H1D + c]; }
        g_h1q[kn] = pk(h[0], h[1]);
        g_h1q[KBATCH * NN + kn] = pk(h[2], h[3]);
        g_f1p1[kn] = pk(__expf(f1), __expf(0.01f * f1));
        g_f2p1[kn] = pk(__expf(f2), __expf(0.01f * f2));
    }
}

// ---------------- attention (layer templated); layer1 fuses prep2 epilogue ----------------
// Inner loop identical to R6 (scalar ull LDS, bit masks). Layer1: RPW=8. Layer2: RPW=4.
template <int LAYER>
__global__ void __launch_bounds__(256, 3) attn_kernel(const float* __restrict__ W2,
                                                      const float* __restrict__ a2) {
    constexpr int NP = (LAYER == 1) ? 2 : 4;     // h pairs per node
    constexpr int RPW = (LAYER == 1) ? 8 : 4;    // rows per warp
    __shared__ ull fs[NN];
    __shared__ ull vs[NP][NN];
    __shared__ float w2s[H1D * DOUT + 2 * DOUT];

    const int k = blockIdx.y;
    const int tid = threadIdx.x;

    const ull* fk = (LAYER == 1 ? g_f2p1 : g_f2p2) + k * NN;
#pragma unroll
    for (int idx = tid; idx < NN; idx += 256) fs[idx] = fk[idx];
    const ull* hq = (LAYER == 1) ? g_h1q : g_h2q;
#pragma unroll
    for (int idx = tid; idx < NN * NP; idx += 256) {
        int q = idx >> 10, j = idx & (NN - 1);
        vs[q][j] = hq[q * (KBATCH * NN) + k * NN + j];
    }
    if (LAYER == 1 && tid < H1D * DOUT + 2 * DOUT)
        w2s[tid] = (tid < H1D * DOUT) ? W2[tid] : a2[tid - H1D * DOUT];
    __syncthreads();

    const int warp = tid >> 5, lane = tid & 31;
    const int i0 = blockIdx.x * (8 * RPW) + warp * RPW;

    ull e1[RPW];
    unsigned tw[RPW];
    float z[RPW];
    ull acc[RPW][NP];
    const ull* f1u = (LAYER == 1) ? g_f1p1 : g_f1p2;
#pragma unroll
    for (int r = 0; r < RPW; r++) {
        e1[r] = f1u[k * NN + i0 + r];
        tw[r] = g_adjT[(i0 + r) * 32 + lane];
        z[r] = 0.f;
#pragma unroll
        for (int q = 0; q < NP; q++) acc[r][q] = 0ull;
    }

#pragma unroll 8
    for (int jj = 0; jj < 32; jj++) {
        ull ef = fs[jj * 32 + lane];
        ull hv[NP];
#pragma unroll
        for (int q = 0; q < NP; q++) hv[q] = vs[q][jj * 32 + lane];
#pragma unroll
        for (int r = 0; r < RPW; r++) {
            ull ab = mul2(e1[r], ef);
            float p = fmaxf(lo2(ab), hi2(ab));            // exp(leaky_relu(f1+f2))
            unsigned m = (unsigned)(((int)(tw[r] << (31 - jj))) >> 31);
            unsigned pu = __float_as_uint(p) & m;
            ull pp = bcast2(pu);
            z[r] += __uint_as_float(pu);
#pragma unroll
            for (int q = 0; q < NP; q++) acc[r][q] = fma2(pp, hv[q], acc[r][q]);
        }
    }

    // butterfly reductions
#pragma unroll
    for (int r = 0; r < RPW; r++) {
#pragma unroll
        for (int o = 16; o; o >>= 1) {
            z[r] += __shfl_xor_sync(0xffffffffu, z[r], o);
#pragma unroll
            for (int q = 0; q < NP; q++) acc[r][q] = add2(acc[r][q], shfl2(acc[r][q], o));
        }
    }

    if (lane < RPW) {
        ull A[NP]; float Z;
#pragma unroll
        for (int r = 0; r < RPW; r++)
            if (lane == r) {
                Z = z[r];
#pragma unroll
                for (int q = 0; q < NP; q++) A[q] = acc[r][q];
            }
        float invz = (Z > 0.f) ? 1.f / Z : 0.f;
        int gi = k * NN + i0 + lane;
        if (LAYER == 1) {
            float h0 = fmaxf(lo2(A[0]) * invz, 0.f);
            float h1 = fmaxf(hi2(A[0]) * invz, 0.f);
            float h2 = fmaxf(lo2(A[1]) * invz, 0.f);
            float h3 = fmaxf(hi2(A[1]) * invz, 0.f);
            float hh[DOUT];
#pragma unroll
            for (int o = 0; o < DOUT; o++)
                hh[o] = h0 * w2s[o] + h1 * w2s[DOUT + o] + h2 * w2s[2 * DOUT + o] + h3 * w2s[3 * DOUT + o];
            float f1 = 0.f, f2 = 0.f;
#pragma unroll
            for (int o = 0; o < DOUT; o++) {
                f1 += hh[o] * w2s[H1D * DOUT + o];
                f2 += hh[o] * w2s[H1D * DOUT + DOUT + o];
            }
#pragma unroll
            for (int q = 0; q < 4; q++)
                g_h2q[q * (KBATCH * NN) + gi] = pk(hh[2 * q], hh[2 * q + 1]);
            g_f1p2[gi] = pk(__expf(f1), __expf(0.01f * f1));
            g_f2p2[gi] = pk(__expf(f2), __expf(0.01f * f2));
        } else {
#pragma unroll
            for (int q = 0; q < NP; q++)
                g_g4[gi * 4 + q] = pk(fmaxf(lo2(A[q]) * invz, 0.f),
                                      fmaxf(hi2(A[q]) * invz, 0.f));
        }
    }
}

// ---------------- head: fc1 split-K GEMM, partial outputs (no atomics) ----------------
#define FBLK 64
__global__ void __launch_bounds__(256) head_fc1_kernel(const float* __restrict__ fc1w) {
    __shared__ float gs[KBATCH][FBLK + 1];
    __shared__ float ws[FBLK][56];
    const int t = threadIdx.x;
    const int d0 = blockIdx.x * FBLK;
    const float* gg = reinterpret_cast<const float*>(g_g4);

#pragma unroll
    for (int idx = t; idx < KBATCH * (FBLK / 4); idx += 256) {
        int k = idx / (FBLK / 4), v = idx % (FBLK / 4);
        float4 x = *reinterpret_cast<const float4*>(gg + k * (NN * DOUT) + d0 + 4 * v);
        gs[k][4 * v + 0] = x.x; gs[k][4 * v + 1] = x.y;
        gs[k][4 * v + 2] = x.z; gs[k][4 * v + 3] = x.w;
    }
    for (int idx = t; idx < FBLK * FC1D; idx += 256) {
        int d = idx / FC1D, c = idx % FC1D;
        ws[d][c] = fc1w[d0 * FC1D + idx];
    }
    __syncthreads();

    const int k = t & 63;
    const int cg = t >> 6;
    ull acc[7] = {0ull, 0ull, 0ull, 0ull, 0ull, 0ull, 0ull};

#pragma unroll 4
    for (int d = 0; d < FBLK; d++) {
        ull g2 = bcast2(__float_as_uint(gs[k][d]));
        const ull* w2 = reinterpret_cast<const ull*>(&ws[d][cg * 14]);
#pragma unroll
        for (int q = 0; q < 7; q++) acc[q] = fma2(g2, w2[q], acc[q]);
    }

    float* dst = g_xp + (size_t)blockIdx.x * FC1D * KBATCH;
    const int cbase = cg * 14;
#pragma unroll
    for (int q = 0; q < 7; q++) {
        int c = cbase + 2 * q;
        if (c < FC1D)     dst[c * KBATCH + k] = lo2(acc[q]);
        if (c + 1 < FC1D) dst[(c + 1) * KBATCH + k] = hi2(acc[q]);
    }
}

// ---------------- head_out: reduce partials + bias/relu + GEMV ----------------
__global__ void __launch_bounds__(256) head_out_kernel(const float* __restrict__ fc1b,
                                                       const float* __restrict__ outw,
                                                       const float* __restrict__ outb,
                                                       float* __restrict__ out) {
    __shared__ float part[4][FC1D];
    __shared__ float xs[FC1D];
    const int k = blockIdx.y;
    const int t = threadIdx.x;

    if (t < 4 * FC1D) {
        const int c = t % FC1D, q = t / FC1D;
        float s = 0.f;
#pragma unroll 8
        for (int d = q * 32; d < q * 32 + 32; d++)
            s += g_xp[((size_t)d * FC1D + c) * KBATCH + k];
        part[q][c] = s;
    }
    __syncthreads();
    if (t < FC1D)
        xs[t] = fmaxf(part[0][t] + part[1][t] + part[2][t] + part[3][t] + fc1b[t], 0.f);
    __syncthreads();

    const int n = blockIdx.x * 256 + t;
    float s = outb[n];
#pragma unroll
    for (int c = 0; c < FC1D; c++) s += xs[c] * outw[c * NN + n];
    out[k * NN + n] = s;
}

// ---------------- launch ----------------
extern "C" void kernel_launch(void* const* d_in, const int* in_sizes, int n_in,
                              void* d_out, int out_size) {
    const float* X    = (const float*)d_in[0];
    const int*   adj  = (const int*)d_in[1];
    const float* W1   = (const float*)d_in[2];
    const float* a1   = (const float*)d_in[3];
    const float* W2   = (const float*)d_in[4];
    const float* a2   = (const float*)d_in[5];
    const float* fc1w = (const float*)d_in[6];
    const float* fc1b = (const float*)d_in[7];
    const float* outw = (const float*)d_in[8];
    const float* outb = (const float*)d_in[9];
    float* out = (float*)d_out;

    prologue_kernel<<<384, 256>>>(adj, X, W1, a1);
    {
        dim3 grid1(NN / 64, KBATCH);   // RPW=8 -> 64 rows per block
        attn_kernel<1><<<grid1, 256>>>(W2, a2);
        dim3 grid2(NN / 32, KBATCH);   // RPW=4 -> 32 rows per block
        attn_kernel<2><<<grid2, 256>>>(W2, a2);
    }
    head_fc1_kernel<<<(NN * DOUT) / FBLK, 256>>>(fc1w);
    {
        dim3 grid(NN / 256, KBATCH);
        head_out_kernel<<<grid, 256>>>(fc1b, outw, outb, out);
    }
}

// round 9
// speedup vs baseline: 1.9736x; 1.1152x over previous
#include <cuda_runtime.h>

#define KBATCH 64
#define NN 1024
#define DIN 16
#define H1D 4
#define DOUT 8
#define FC1D 54

typedef unsigned long long ull;

// ---------------- scratch (static device memory) ----------------
__device__ unsigned g_adjT[NN * 32];            // word (i,l) bit jj = adj[i][jj*32+l]
__device__ ull g_h1q[2 * KBATCH * NN];          // layer1 h pairs, SoA: [q][k*N+n]
__device__ ull g_h2q[4 * KBATCH * NN];          // layer2 h pairs, SoA
__device__ ull g_f1p1[KBATCH * NN];             // {e^f1, e^{0.01 f1}}
__device__ ull g_f2p1[KBATCH * NN];
__device__ ull g_f1p2[KBATCH * NN];
__device__ ull g_f2p2[KBATCH * NN];
__device__ ull g_g4[KBATCH * NN * 4];           // relu(gat2) pairs == [K][8192] floats
__device__ float g_xp[256 * FC1D * 32];         // fc1 partials [dchunk*2+khalf][c][k%32]

// ---------------- f32x2 helpers ----------------
__device__ __forceinline__ ull mul2(ull a, ull b) {
    ull r; asm("mul.rn.f32x2 %0,%1,%2;" : "=l"(r) : "l"(a), "l"(b)); return r;
}
__device__ __forceinline__ ull fma2(ull a, ull b, ull c) {
    ull r; asm("fma.rn.f32x2 %0,%1,%2,%3;" : "=l"(r) : "l"(a), "l"(b), "l"(c)); return r;
}
__device__ __forceinline__ ull add2(ull a, ull b) {
    ull r; asm("add.rn.f32x2 %0,%1,%2;" : "=l"(r) : "l"(a), "l"(b)); return r;
}
__device__ __forceinline__ float lo2(ull v) { return __uint_as_float((unsigned)v); }
__device__ __forceinline__ float hi2(ull v) { return __uint_as_float((unsigned)(v >> 32)); }
__device__ __forceinline__ ull pk(float x, float y) {
    return (ull)__float_as_uint(x) | ((ull)__float_as_uint(y) << 32);
}
__device__ __forceinline__ ull bcast2(unsigned v) {
    ull r; asm("mov.b64 %0,{%1,%1};" : "=l"(r) : "r"(v)); return r;
}
__device__ __forceinline__ ull shfl2(ull v, int o) {
    unsigned l = (unsigned)v, h = (unsigned)(v >> 32);
    l = __shfl_xor_sync(0xffffffffu, l, o);
    h = __shfl_xor_sync(0xffffffffu, h, o);
    return (ull)l | ((ull)h << 32);
}

// ---------------- prologue: pack adj + prep1 ----------------
__global__ void prologue_kernel(const int* __restrict__ adj,
                                const float* __restrict__ X,
                                const float* __restrict__ W1,
                                const float* __restrict__ a1) {
    __shared__ float w[DIN * H1D];
    __shared__ float a[2 * H1D];
    int b = blockIdx.x, t = threadIdx.x;
    if (b < 128) {
        int warp = t >> 5, lane = t & 31;
        int i = b * 8 + warp;
        unsigned acc = 0;
#pragma unroll
        for (int jj = 0; jj < 32; jj++) {
            int v = adj[i * NN + jj * 32 + lane];
            acc |= (v > 0 ? 1u : 0u) << jj;
        }
        g_adjT[i * 32 + lane] = acc;
    } else {
        if (t < DIN * H1D) w[t] = W1[t];
        if (t < 2 * H1D) a[t] = a1[t];
        __syncthreads();
        int kn = (b - 128) * 256 + t;
        const float4* x4 = reinterpret_cast<const float4*>(X) + kn * 4;
        float h[H1D] = {0.f, 0.f, 0.f, 0.f};
#pragma unroll
        for (int q = 0; q < 4; q++) {
            float4 xv = x4[q];
            float xs[4] = {xv.x, xv.y, xv.z, xv.w};
#pragma unroll
            for (int d = 0; d < 4; d++)
#pragma unroll
                for (int c = 0; c < H1D; c++)
                    h[c] += xs[d] * w[(q * 4 + d) * H1D + c];
        }
        float f1 = 0.f, f2 = 0.f;
#pragma unroll
        for (int c = 0; c < H1D; c++) { f1 += h[c] * a[c]; f2 += h[c] * a[H1D + c]; }
        g_h1q[kn] = pk(h[0], h[1]);
        g_h1q[KBATCH * NN + kn] = pk(h[2], h[3]);
        g_f1p1[kn] = pk(__expf(f1), __expf(0.01f * f1));
        g_f2p1[kn] = pk(__expf(f2), __expf(0.01f * f2));
    }
}

// ---------------- attention; layer1 fuses prep2 epilogue ----------------
// Inner loop identical to R6 (scalar ull LDS, bit masks).
// Layer1: RPW=4, 3 blocks/SM. Layer2: RPW=8, 2 blocks/SM (128-reg budget).
template <int LAYER>
__global__ void __launch_bounds__(256, (LAYER == 1) ? 3 : 2)
attn_kernel(const float* __restrict__ W2, const float* __restrict__ a2) {
    constexpr int NP = (LAYER == 1) ? 2 : 4;     // h pairs per node
    constexpr int RPW = (LAYER == 1) ? 4 : 8;    // rows per warp
    __shared__ ull fs[NN];
    __shared__ ull vs[NP][NN];
    __shared__ float w2s[H1D * DOUT + 2 * DOUT];

    const int k = blockIdx.y;
    const int tid = threadIdx.x;

    const ull* fk = (LAYER == 1 ? g_f2p1 : g_f2p2) + k * NN;
#pragma unroll
    for (int idx = tid; idx < NN; idx += 256) fs[idx] = fk[idx];
    const ull* hq = (LAYER == 1) ? g_h1q : g_h2q;
#pragma unroll
    for (int idx = tid; idx < NN * NP; idx += 256) {
        int q = idx >> 10, j = idx & (NN - 1);
        vs[q][j] = hq[q * (KBATCH * NN) + k * NN + j];
    }
    if (LAYER == 1 && tid < H1D * DOUT + 2 * DOUT)
        w2s[tid] = (tid < H1D * DOUT) ? W2[tid] : a2[tid - H1D * DOUT];
    __syncthreads();

    const int warp = tid >> 5, lane = tid & 31;
    const int i0 = blockIdx.x * (8 * RPW) + warp * RPW;

    ull e1[RPW];
    unsigned tw[RPW];
    float z[RPW];
    ull acc[RPW][NP];
    const ull* f1u = (LAYER == 1) ? g_f1p1 : g_f1p2;
#pragma unroll
    for (int r = 0; r < RPW; r++) {
        e1[r] = f1u[k * NN + i0 + r];
        tw[r] = g_adjT[(i0 + r) * 32 + lane];
        z[r] = 0.f;
#pragma unroll
        for (int q = 0; q < NP; q++) acc[r][q] = 0ull;
    }

#pragma unroll 8
    for (int jj = 0; jj < 32; jj++) {
        ull ef = fs[jj * 32 + lane];
        ull hv[NP];
#pragma unroll
        for (int q = 0; q < NP; q++) hv[q] = vs[q][jj * 32 + lane];
#pragma unroll
        for (int r = 0; r < RPW; r++) {
            ull ab = mul2(e1[r], ef);
            float p = fmaxf(lo2(ab), hi2(ab));            // exp(leaky_relu(f1+f2))
            unsigned m = (unsigned)(((int)(tw[r] << (31 - jj))) >> 31);
            unsigned pu = __float_as_uint(p) & m;
            ull pp = bcast2(pu);
            z[r] += __uint_as_float(pu);
#pragma unroll
            for (int q = 0; q < NP; q++) acc[r][q] = fma2(pp, hv[q], acc[r][q]);
        }
    }

    // butterfly reductions
#pragma unroll
    for (int r = 0; r < RPW; r++) {
#pragma unroll
        for (int o = 16; o; o >>= 1) {
            z[r] += __shfl_xor_sync(0xffffffffu, z[r], o);
#pragma unroll
            for (int q = 0; q < NP; q++) acc[r][q] = add2(acc[r][q], shfl2(acc[r][q], o));
        }
    }

    if (lane < RPW) {
        ull A[NP]; float Z;
#pragma unroll
        for (int r = 0; r < RPW; r++)
            if (lane == r) {
                Z = z[r];
#pragma unroll
                for (int q = 0; q < NP; q++) A[q] = acc[r][q];
            }
        float invz = (Z > 0.f) ? 1.f / Z : 0.f;
        int gi = k * NN + i0 + lane;
        if (LAYER == 1) {
            float h0 = fmaxf(lo2(A[0]) * invz, 0.f);
            float h1 = fmaxf(hi2(A[0]) * invz, 0.f);
            float h2 = fmaxf(lo2(A[1]) * invz, 0.f);
            float h3 = fmaxf(hi2(A[1]) * invz, 0.f);
            float hh[DOUT];
#pragma unroll
            for (int o = 0; o < DOUT; o++)
                hh[o] = h0 * w2s[o] + h1 * w2s[DOUT + o] + h2 * w2s[2 * DOUT + o] + h3 * w2s[3 * DOUT + o];
            float f1 = 0.f, f2 = 0.f;
#pragma unroll
            for (int o = 0; o < DOUT; o++) {
                f1 += hh[o] * w2s[H1D * DOUT + o];
                f2 += hh[o] * w2s[H1D * DOUT + DOUT + o];
            }
#pragma unroll
            for (int q = 0; q < 4; q++)
                g_h2q[q * (KBATCH * NN) + gi] = pk(hh[2 * q], hh[2 * q + 1]);
            g_f1p2[gi] = pk(__expf(f1), __expf(0.01f * f1));
            g_f2p2[gi] = pk(__expf(f2), __expf(0.01f * f2));
        } else {
#pragma unroll
            for (int q = 0; q < NP; q++)
                g_g4[gi * 4 + q] = pk(fmaxf(lo2(A[q]) * invz, 0.f),
                                      fmaxf(hi2(A[q]) * invz, 0.f));
        }
    }
}

// ---------------- head: fc1 split-K GEMM (d-chunk x k-half), no atomics ----------------
#define FBLK 64
__global__ void __launch_bounds__(256) head_fc1_kernel(const float* __restrict__ fc1w) {
    __shared__ float gs[32][FBLK + 1];        // 32 k x 64 d
    __shared__ float ws[FBLK][64];            // [d][c] (padded to 64)
    const int t = threadIdx.x;
    const int d0 = blockIdx.x * FBLK;
    const int k0 = blockIdx.y * 32;
    const float* gg = reinterpret_cast<const float*>(g_g4);

    // stage g tile: 32 k x 64 d (512 float4 loads)
#pragma unroll
    for (int idx = t; idx < 32 * (FBLK / 4); idx += 256) {
        int k = idx / (FBLK / 4), v = idx % (FBLK / 4);
        float4 x = *reinterpret_cast<const float4*>(gg + (k0 + k) * (NN * DOUT) + d0 + 4 * v);
        gs[k][4 * v + 0] = x.x; gs[k][4 * v + 1] = x.y;
        gs[k][4 * v + 2] = x.z; gs[k][4 * v + 3] = x.w;
    }
    // stage w tile: 64 d x 54 c
    for (int idx = t; idx < FBLK * FC1D; idx += 256) {
        int d = idx / FC1D, c = idx % FC1D;
        ws[d][c] = fc1w[d0 * FC1D + idx];
    }
    __syncthreads();

    const int k = t & 31;        // lane k within this k-half
    const int cg = t >> 5;       // 0..7 -> c base = cg*8
    ull acc[4] = {0ull, 0ull, 0ull, 0ull};

#pragma unroll 4
    for (int d = 0; d < FBLK; d++) {
        ull g2 = bcast2(__float_as_uint(gs[k][d]));
        const ull* w2 = reinterpret_cast<const ull*>(&ws[d][cg * 8]);
#pragma unroll
        for (int q = 0; q < 4; q++) acc[q] = fma2(g2, w2[q], acc[q]);
    }

    // partial store: g_xp[(dchunk*2+khalf)][c][k]
    float* dst = g_xp + (size_t)(blockIdx.x * 2 + blockIdx.y) * FC1D * 32;
    const int cbase = cg * 8;
#pragma unroll
    for (int q = 0; q < 4; q++) {
        int c = cbase + 2 * q;
        if (c < FC1D)     dst[c * 32 + k] = lo2(acc[q]);
        if (c + 1 < FC1D) dst[(c + 1) * 32 + k] = hi2(acc[q]);
    }
}

// ---------------- head_out: reduce partials + bias/relu + GEMV ----------------
__global__ void __launch_bounds__(256) head_out_kernel(const float* __restrict__ fc1b,
                                                       const float* __restrict__ outw,
                                                       const float* __restrict__ outb,
                                                       float* __restrict__ out) {
    __shared__ float part[4][FC1D];
    __shared__ float xs[FC1D];
    const int k = blockIdx.y;
    const int t = threadIdx.x;
    const int khalf = k >> 5, kk = k & 31;

    if (t < 4 * FC1D) {
        const int c = t % FC1D, q = t / FC1D;
        float s = 0.f;
#pragma unroll 8
        for (int d = q * 32; d < q * 32 + 32; d++)
            s += g_xp[((size_t)(d * 2 + khalf) * FC1D + c) * 32 + kk];
        part[q][c] = s;
    }
    __syncthreads();
    if (t < FC1D)
        xs[t] = fmaxf(part[0][t] + part[1][t] + part[2][t] + part[3][t] + fc1b[t], 0.f);
    __syncthreads();

    const int n = blockIdx.x * 256 + t;
    float s = outb[n];
#pragma unroll
    for (int c = 0; c < FC1D; c++) s += xs[c] * outw[c * NN + n];
    out[k * NN + n] = s;
}

// ---------------- launch ----------------
extern "C" void kernel_launch(void* const* d_in, const int* in_sizes, int n_in,
                              void* d_out, int out_size) {
    const float* X    = (const float*)d_in[0];
    const int*   adj  = (const int*)d_in[1];
    const float* W1   = (const float*)d_in[2];
    const float* a1   = (const float*)d_in[3];
    const float* W2   = (const float*)d_in[4];
    const float* a2   = (const float*)d_in[5];
    const float* fc1w = (const float*)d_in[6];
    const float* fc1b = (const float*)d_in[7];
    const float* outw = (const float*)d_in[8];
    const float* outb = (const float*)d_in[9];
    float* out = (float*)d_out;

    prologue_kernel<<<384, 256>>>(adj, X, W1, a1);
    {
        dim3 grid1(NN / 32, KBATCH);   // layer1: RPW=4 -> 32 rows/block
        attn_kernel<1><<<grid1, 256>>>(W2, a2);
        dim3 grid2(NN / 64, KBATCH);   // layer2: RPW=8 -> 64 rows/block
        attn_kernel<2><<<grid2, 256>>>(W2, a2);
    }
    {
        dim3 gridf((NN * DOUT) / FBLK, 2);   // 128 d-chunks x 2 k-halves
        head_fc1_kernel<<<gridf, 256>>>(fc1w);
    }
    {
        dim3 grid(NN / 256, KBATCH);
        head_out_kernel<<<grid, 256>>>(fc1b, outw, outb, out);
    }
}